// round 15
// baseline (speedup 1.0000x reference)
#include <cuda_runtime.h>
#include <cuda_fp16.h>
#include <math.h>

#define PB  256
#define PTc 64
#define NP  16384      // N = P*PT
#define M2  32768      // 2N
#define R2C 0.09f

// ---------------- scratch (static device globals; no allocations) ------------
__device__ float g_lf_s1[PB * 256];          // includes +sb1 (folded in k_red2)
__device__ float g_lf_m1[PB * 512];
__device__ float g_npos[NP * 3];
__device__ int   g_nbr[M2 * 9];
__device__ float g_U[(size_t)M2 * 64];
__device__ float g_V[(size_t)M2 * 64];
__device__ __half2 g_posfeah[(size_t)M2 * 64];   // pos_fea, K-pair packed
__device__ __half2 g_g1h[(size_t)M2 * 256];      // g1, K-pair packed
__device__ float g_part[6 * 256 * 768];
__device__ __half2 g_wt1h[64 * 512];    // mw1[768:] K-pair packed fp16
__device__ __half2 g_wt2h[256 * 256];   // mw2 K-pair packed fp16
__device__ __half2 g_wt3h[32 * 128];    // cw2 K-pair packed fp16
__device__ __half2 g_w2hh[128 * 128];   // sw2 hi, K-pair packed
__device__ __half2 g_w2lh[128 * 128];   // sw2 lo residual, K-pair packed

#define MMA_F16(cc, aa, bb) \
    asm volatile("mma.sync.aligned.m16n8k16.row.col.f32.f16.f16.f32 " \
        "{%0,%1,%2,%3},{%4,%5,%6,%7},{%8,%9},{%0,%1,%2,%3};" \
        : "+f"(cc[0]), "+f"(cc[1]), "+f"(cc[2]), "+f"(cc[3]) \
        : "r"(aa[0]), "r"(aa[1]), "r"(aa[2]), "r"(aa[3]), "r"(bb[0]), "r"(bb[1]))

__device__ __forceinline__ void cp16(void* dst, const void* src) {
    unsigned d = (unsigned)__cvta_generic_to_shared(dst);
    asm volatile("cp.async.cg.shared.global [%0], [%1], 16;" :: "r"(d), "l"(src));
}

__device__ __forceinline__ unsigned h2u(__half2 h) {
    union { __half2 h; unsigned u; } v; v.h = h; return v.u;
}

// ------- fused lf GEMM: A=lfea[256x768], virtual B = [sw1 | mw1] (N=768) -----
__global__ void gemm_sk2(const float* __restrict__ A, const float* __restrict__ sw1,
                         const float* __restrict__ mw1)
{
    __shared__ float As[64][17];
    __shared__ float Bs[16][65];
    const int bm = blockIdx.y * 64, bn = blockIdx.x * 64;
    const float* B; int Nn, coloff;
    if (bn < 256) { B = sw1; Nn = 256; coloff = bn; }
    else          { B = mw1; Nn = 512; coloff = bn - 256; }
    const int t = threadIdx.x;
    const int ty = t >> 4, tx = t & 15;
    float acc[4][4] = {};
    int kbeg = blockIdx.z * 128, kend = kbeg + 128;
    for (int k0 = kbeg; k0 < kend; k0 += 16) {
        #pragma unroll
        for (int i = 0; i < 4; i++) {
            int e = t + i * 256; int r = e >> 4, c = e & 15;
            As[r][c] = A[(size_t)(bm + r) * 768 + k0 + c];
        }
        #pragma unroll
        for (int i = 0; i < 4; i++) {
            int e = t + i * 256; int r = e >> 6, c = e & 63;
            Bs[r][c] = B[(size_t)(k0 + r) * Nn + coloff + c];
        }
        __syncthreads();
        #pragma unroll
        for (int kk = 0; kk < 16; kk++) {
            float a[4], b[4];
            #pragma unroll
            for (int i = 0; i < 4; i++) a[i] = As[ty * 4 + i][kk];
            #pragma unroll
            for (int j = 0; j < 4; j++) b[j] = Bs[kk][tx * 4 + j];
            #pragma unroll
            for (int i = 0; i < 4; i++)
                #pragma unroll
                for (int j = 0; j < 4; j++)
                    acc[i][j] += a[i] * b[j];
        }
        __syncthreads();
    }
    float* Cz = g_part + (size_t)blockIdx.z * 256 * 768;
    #pragma unroll
    for (int i = 0; i < 4; i++)
        #pragma unroll
        for (int j = 0; j < 4; j++)
            Cz[(size_t)(bm + ty * 4 + i) * 768 + bn + tx * 4 + j] = acc[i][j];
}

// ------- reduce split-K + (folded) weight packing + sb1 fold -----------------
__global__ void k_red2(const float* __restrict__ sb1, const float* __restrict__ w1,
                       const float* __restrict__ w2, const float* __restrict__ w3,
                       const float* __restrict__ sw2)
{
    int e = blockIdx.x * 256 + threadIdx.x;   // < 196608
    float s = 0.f;
    #pragma unroll
    for (int z = 0; z < 6; z++) s += g_part[(size_t)z * 196608 + e];
    int row = e / 768, col = e - row * 768;
    if (col < 256) g_lf_s1[row * 256 + col] = s + sb1[col];
    else           g_lf_m1[row * 512 + col - 256] = s;

    // folded weight packing (same thread-id space)
    int i = e;
    if (i < 32768) {                       // wt1h: [64 kk][512 n]
        int kk = i >> 9, n = i & 511;
        g_wt1h[i] = __floats2half2_rn(w1[(2 * kk) * 512 + n], w1[(2 * kk + 1) * 512 + n]);
    } else if (i < 98304) {                // wt2h: [256 kk][256 n]
        int e2 = i - 32768; int kk = e2 >> 8, n = e2 & 255;
        g_wt2h[e2] = __floats2half2_rn(w2[(2 * kk) * 256 + n], w2[(2 * kk + 1) * 256 + n]);
    } else if (i < 102400) {               // wt3h: [32 kk][128 n]
        int e2 = i - 98304; int kk = e2 >> 7, n = e2 & 127;
        g_wt3h[e2] = __floats2half2_rn(w3[(2 * kk) * 128 + n], w3[(2 * kk + 1) * 128 + n]);
    } else if (i < 118784) {               // sw2 hi/lo: [128 kk][128 n]
        int e2 = i - 102400; int kk = e2 >> 7, n = e2 & 127;
        float f0 = sw2[(2 * kk) * 128 + n], f1 = sw2[(2 * kk + 1) * 128 + n];
        __half h0 = __float2half_rn(f0), h1 = __float2half_rn(f1);
        g_w2hh[e2] = __halves2half2(h0, h1);
        g_w2lh[e2] = __floats2half2_rn(f0 - __half2float(h0), f1 - __half2float(h1));
    }
}

// ------- mega: h1 on-the-fly -> fp16-split h2 GEMM -> n_pos -> KNN -> U/V ----
// block = 128 rows = 2 complete batches; cp.async staged A-inputs + B, 2-deep
__global__ void __launch_bounds__(256)
tc3mega(const float* __restrict__ pos, const float* __restrict__ sw1,
        const float* __restrict__ sb2, const float* __restrict__ sw3,
        const float* __restrict__ sb3, const float* __restrict__ cw1,
        const float* __restrict__ cb1)
{
    extern __shared__ unsigned sm3[];
    unsigned* Ah = sm3;                        // [128][20] half2
    unsigned* Al = Ah + 2560;                  // [128][20]
    unsigned* BhB[2] = { Al + 2560, Al + 2560 + 2176 };          // each [16][136]
    unsigned* BlB[2] = { Al + 2560 + 4352, Al + 2560 + 6528 };   // each [16][136]
    float* stageB = (float*)(Al + 2560 + 8704);                  // 2 x 160 floats
    const int t = threadIdx.x;
    const int warp = t >> 5, lane = t & 31;
    const int g = lane >> 2, q = lane & 3;
    const int wm = warp >> 1, wn = warp & 1;
    const int bm = blockIdx.y * 128;
    const int p0 = bm >> 6;

    float c[2][8][4];
    #pragma unroll
    for (int i = 0; i < 2; i++)
        #pragma unroll
        for (int j = 0; j < 8; j++)
            #pragma unroll
            for (int e = 0; e < 4; e++) c[i][j][e] = 0.f;

    const int rA = t >> 3, c4A = (t & 7) * 4;
    float pxr[4], pyr[4], pzr[4];
    #pragma unroll
    for (int i = 0; i < 4; i++) {
        int row = bm + rA + i * 32;
        pxr[i] = pos[row * 3]; pyr[i] = pos[row * 3 + 1]; pzr[i] = pos[row * 3 + 2];
    }

    // cp.async issue for tile tt (k0 = 32*tt)
    auto issue = [&](int tt) {
        int s = tt & 1;
        int kk0 = tt * 16, k0 = tt * 32;
        #pragma unroll
        for (int i = 0; i < 2; i++) {
            int e = t + i * 256; int r = e >> 5, cu = (e & 31) * 4;
            cp16(&BhB[s][r * 136 + cu], (const unsigned*)g_w2hh + (size_t)(kk0 + r) * 128 + cu);
            cp16(&BlB[s][r * 136 + cu], (const unsigned*)g_w2lh + (size_t)(kk0 + r) * 128 + cu);
        }
        if (t < 40) {
            int seg = t >> 3, off = (t & 7) * 4;
            const float* src;
            if (seg == 0)      src = g_lf_s1 + p0 * 256 + k0 + off;
            else if (seg == 1) src = g_lf_s1 + (p0 + 1) * 256 + k0 + off;
            else               src = sw1 + (size_t)(768 + seg - 2) * 256 + k0 + off;
            cp16(&stageB[s * 160 + seg * 32 + off], src);
        }
    };

    issue(0);
    asm volatile("cp.async.commit_group;");

    for (int tt = 0; tt < 8; tt++) {
        asm volatile("cp.async.wait_group 0;");
        __syncthreads();        // tile tt staged data visible; prev mma done
        if (tt + 1 < 8) {
            issue(tt + 1);      // overlaps fillA + mma below
            asm volatile("cp.async.commit_group;");
        }
        // fillA from staged inputs (all smem reads)
        {
            const float* st = stageB + (tt & 1) * 160;
            float4 w0 = *(const float4*)(st + 64 + c4A);
            float4 w1 = *(const float4*)(st + 96 + c4A);
            float4 w2 = *(const float4*)(st + 128 + c4A);
            float4 lf0 = *(const float4*)(st + c4A);
            float4 lf1 = *(const float4*)(st + 32 + c4A);
            #pragma unroll
            for (int i = 0; i < 4; i++) {
                int r = rA + i * 32;
                float4 lf = (i < 2) ? lf0 : lf1;
                float px = pxr[i], py = pyr[i], pz = pzr[i];
                float h0 = fmaxf(lf.x + px * w0.x + py * w1.x + pz * w2.x, 0.f);
                float h1v = fmaxf(lf.y + px * w0.y + py * w1.y + pz * w2.y, 0.f);
                float h2v = fmaxf(lf.z + px * w0.z + py * w1.z + pz * w2.z, 0.f);
                float h3 = fmaxf(lf.w + px * w0.w + py * w1.w + pz * w2.w, 0.f);
                __half2 hiA = __floats2half2_rn(h0, h1v);
                __half2 hiB = __floats2half2_rn(h2v, h3);
                float2 fA = __half22float2(hiA), fB = __half22float2(hiB);
                __half2 loA = __floats2half2_rn(h0 - fA.x, h1v - fA.y);
                __half2 loB = __floats2half2_rn(h2v - fB.x, h3 - fB.y);
                int idx = r * 20 + (c4A >> 1);
                *(uint2*)&Ah[idx] = make_uint2(h2u(hiA), h2u(hiB));
                *(uint2*)&Al[idx] = make_uint2(h2u(loA), h2u(loB));
            }
        }
        __syncthreads();
        const unsigned* Bh = BhB[tt & 1];
        const unsigned* Bl = BlB[tt & 1];
        #pragma unroll
        for (int ks = 0; ks < 2; ks++) {
            int k8 = ks * 8;
            unsigned ah[2][4], al[2][4];
            #pragma unroll
            for (int mt = 0; mt < 2; mt++) {
                int r = wm * 32 + mt * 16 + g;
                ah[mt][0] = Ah[r * 20 + k8 + q];       al[mt][0] = Al[r * 20 + k8 + q];
                ah[mt][1] = Ah[(r + 8) * 20 + k8 + q]; al[mt][1] = Al[(r + 8) * 20 + k8 + q];
                ah[mt][2] = Ah[r * 20 + k8 + q + 4];   al[mt][2] = Al[r * 20 + k8 + q + 4];
                ah[mt][3] = Ah[(r + 8) * 20 + k8 + q + 4]; al[mt][3] = Al[(r + 8) * 20 + k8 + q + 4];
            }
            #pragma unroll
            for (int nt = 0; nt < 8; nt++) {
                int cn = wn * 64 + nt * 8 + g;
                unsigned bh[2], bl[2];
                bh[0] = Bh[(k8 + q) * 136 + cn];     bh[1] = Bh[(k8 + q + 4) * 136 + cn];
                bl[0] = Bl[(k8 + q) * 136 + cn];     bl[1] = Bl[(k8 + q + 4) * 136 + cn];
                #pragma unroll
                for (int mt = 0; mt < 2; mt++) {
                    MMA_F16(c[mt][nt], al[mt], bh);
                    MMA_F16(c[mt][nt], ah[mt], bl);
                    MMA_F16(c[mt][nt], ah[mt], bh);
                }
            }
        }
    }
    __syncthreads();   // all mma done before smem reuse

    // ---- phase 2: n_pos via smem reduction ----
    float* fsm = (float*)sm3;
    float* sred = fsm;                 // 128*8*3
    float* snp  = fsm + 3072;          // 128*3
    float* sx   = fsm + 3456;          // 256
    float* sy   = fsm + 3712;
    float* sz   = fsm + 3968;
    float* scw1 = fsm + 4224;          // 384
    float* scb1 = fsm + 4608;          // 64
    #pragma unroll
    for (int mt = 0; mt < 2; mt++) {
        #pragma unroll
        for (int half = 0; half < 2; half++) {
            int row_l = wm * 32 + mt * 16 + half * 8 + g;
            float p0v = 0.f, p1 = 0.f, p2 = 0.f;
            #pragma unroll
            for (int nt = 0; nt < 8; nt++) {
                int col = wn * 64 + nt * 8 + q * 2;
                float v0 = fmaxf(c[mt][nt][half * 2 + 0] + sb2[col], 0.f);
                float v1 = fmaxf(c[mt][nt][half * 2 + 1] + sb2[col + 1], 0.f);
                p0v += v0 * sw3[col * 3]     + v1 * sw3[(col + 1) * 3];
                p1 += v0 * sw3[col * 3 + 1] + v1 * sw3[(col + 1) * 3 + 1];
                p2 += v0 * sw3[col * 3 + 2] + v1 * sw3[(col + 1) * 3 + 2];
            }
            int slot = wn * 4 + q;
            sred[(row_l * 8 + slot) * 3 + 0] = p0v;
            sred[(row_l * 8 + slot) * 3 + 1] = p1;
            sred[(row_l * 8 + slot) * 3 + 2] = p2;
        }
    }
    __syncthreads();
    if (t < 128) {
        float a0 = 0.f, a1 = 0.f, a2 = 0.f;
        #pragma unroll
        for (int s = 0; s < 8; s++) {
            a0 += sred[(t * 8 + s) * 3 + 0];
            a1 += sred[(t * 8 + s) * 3 + 1];
            a2 += sred[(t * 8 + s) * 3 + 2];
        }
        int row = bm + t;
        float n0 = tanhf(fmaxf(a0 + sb3[0], 0.f)) + pos[row * 3 + 0];
        float n1 = tanhf(fmaxf(a1 + sb3[1], 0.f)) + pos[row * 3 + 1];
        float n2 = tanhf(fmaxf(a2 + sb3[2], 0.f)) + pos[row * 3 + 2];
        g_npos[row * 3 + 0] = n0; g_npos[row * 3 + 1] = n1; g_npos[row * 3 + 2] = n2;
        snp[t * 3 + 0] = n0; snp[t * 3 + 1] = n1; snp[t * 3 + 2] = n2;
    }
    __syncthreads();

    // ---- phase 3: KNN for the 2 batches + U/V ----
    int b = t >> 7, i = t & 127;
    int rowl = b * 64 + (i & 63);
    float x, y, z;
    if (i < 64) {
        int gr = bm + rowl;
        x = pos[gr * 3]; y = pos[gr * 3 + 1]; z = pos[gr * 3 + 2];
    } else {
        x = snp[rowl * 3]; y = snp[rowl * 3 + 1]; z = snp[rowl * 3 + 2];
    }
    sx[b * 128 + i] = x; sy[b * 128 + i] = y; sz[b * 128 + i] = z;
    for (int e = t; e < 448; e += 256) {
        if (e < 384) scw1[e] = cw1[e]; else scb1[e - 384] = cb1[e - 384];
    }
    __syncthreads();

    unsigned long long bk[9];
    #pragma unroll
    for (int qq = 0; qq < 9; qq++) bk[qq] = 0xFFFFFFFFFFFFFFFFull;
    const float* sxb = sx + b * 128; const float* syb = sy + b * 128; const float* szb = sz + b * 128;
    for (int j = 0; j < 128; j++) {
        float dx = x - sxb[j], dy = y - syb[j], dz = z - szb[j];
        float d2 = dx * dx + dy * dy + dz * dz;
        if (d2 <= R2C) {
            unsigned long long key = ((unsigned long long)__float_as_uint(d2) << 32) | (unsigned)j;
            if (key < bk[8]) {
                bk[8] = key;
                #pragma unroll
                for (int qq = 8; qq > 0; qq--)
                    if (bk[qq] < bk[qq - 1]) {
                        unsigned long long tmp = bk[qq]; bk[qq] = bk[qq - 1]; bk[qq - 1] = tmp;
                    }
            }
        }
    }
    int ptg = (p0 + b) * 128 + i;
    int bi0 = (int)(unsigned)bk[0];
    #pragma unroll
    for (int qq = 0; qq < 9; qq++)
        g_nbr[ptg * 9 + qq] = (bk[qq] != 0xFFFFFFFFFFFFFFFFull) ? (int)(unsigned)bk[qq] : bi0;

    for (int e = t; e < 256 * 64; e += 256) {
        int ptl = e >> 6, k = e & 63;
        float xx = sx[ptl], yy = sy[ptl], zz = sz[ptl];
        float wn0 = scw1[k],       wn1 = scw1[64 + k],  wn2 = scw1[128 + k];
        float wr0 = scw1[192 + k], wr1 = scw1[256 + k], wr2 = scw1[320 + k];
        int ptgl = (p0 + (ptl >> 7)) * 128 + (ptl & 127);
        g_U[(size_t)ptgl * 64 + k] = scb1[k] + xx * (wn0 + wr0) + yy * (wn1 + wr1) + zz * (wn2 + wr2);
        g_V[(size_t)ptgl * 64 + k] = xx * wr0 + yy * wr1 + zz * wr2;
    }
}

// ------------- edge MLP phase-B: cp.async-staged gather + fp16 mma -----------
__global__ void __launch_bounds__(256)
k_edge2(const float* __restrict__ cb2)
{
    extern __shared__ unsigned esm[];
    unsigned* Bs = esm;                                        // [32][136] half2
    unsigned* Abuf[2] = { esm + 4352, esm + 4352 + 2304 };     // each [64][36] half2
    float* rawU[2] = { (float*)(esm + 8960), (float*)(esm + 8960 + 4096) }; // each [64][64]
    const int t = threadIdx.x;
    const int warp = t >> 5, lane = t & 31;
    const int g = lane >> 2, q = lane & 3;
    const int wm = warp >> 1, wn = warp & 1;
    const int p = blockIdx.x >> 1, half = blockIdx.x & 1;
    const int ptbase = p * 128 + half * 64;
    const int r4 = t >> 2, q4 = t & 3;

    // per-thread neighbor indices (row r4's 9 neighbors; 4 threads/row redundant but cheap)
    int nbr9[9];
    #pragma unroll
    for (int qq = 0; qq < 9; qq++) nbr9[qq] = g_nbr[(ptbase + r4) * 9 + qq];

    for (int e = t; e < 32 * 128; e += 256)
        Bs[(e >> 7) * 136 + (e & 127)] = ((const unsigned*)g_wt3h)[e];

    float vv[16];
    {
        const float4* Vr = (const float4*)(g_V + (size_t)(ptbase + r4) * 64 + q4 * 16);
        #pragma unroll
        for (int j4 = 0; j4 < 4; j4++) {
            float4 v = Vr[j4];
            vv[j4 * 4 + 0] = v.x; vv[j4 * 4 + 1] = v.y;
            vv[j4 * 4 + 2] = v.z; vv[j4 * 4 + 3] = v.w;
        }
    }

    // async gather of neighbor U rows into raw stage s
    auto gather = [&](int qn, int s) {
        const float* Ur = g_U + (size_t)(p * 128 + nbr9[qn]) * 64 + q4 * 16;
        float* dst = rawU[s] + r4 * 64 + q4 * 16;
        cp16(dst, Ur); cp16(dst + 4, Ur + 4);
        cp16(dst + 8, Ur + 8); cp16(dst + 12, Ur + 12);
    };

    gather(0, 0); asm volatile("cp.async.commit_group;");
    gather(1, 1); asm volatile("cp.async.commit_group;");

    float mx[8][4];
    #pragma unroll 1
    for (int qn = 0; qn < 9; qn++) {
        if (qn < 8) { asm volatile("cp.async.wait_group 1;"); }
        else        { asm volatile("cp.async.wait_group 0;"); }
        __syncthreads();   // raw[qn&1] visible; mma of qn-1 done
        // convert raw -> Abuf (smem-only)
        {
            const float* Rr = rawU[qn & 1] + r4 * 64 + q4 * 16;
            union { __half2 h[4]; uint4 u; } pk;
            #pragma unroll
            for (int j4 = 0; j4 < 2; j4++) {
                #pragma unroll
                for (int s = 0; s < 2; s++) {
                    float4 u = *(const float4*)(Rr + (j4 * 2 + s) * 4);
                    pk.h[s * 2 + 0] = __floats2half2_rn(fmaxf(u.x - vv[(j4 * 2 + s) * 4 + 0], 0.f),
                                                        fmaxf(u.y - vv[(j4 * 2 + s) * 4 + 1], 0.f));
                    pk.h[s * 2 + 1] = __floats2half2_rn(fmaxf(u.z - vv[(j4 * 2 + s) * 4 + 2], 0.f),
                                                        fmaxf(u.w - vv[(j4 * 2 + s) * 4 + 3], 0.f));
                }
                *(uint4*)&Abuf[qn & 1][r4 * 36 + q4 * 8 + j4 * 4] = pk.u;
            }
        }
        __syncthreads();   // Abuf ready; raw[qn&1] free for reuse
        if (qn + 2 < 9) {
            gather(qn + 2, qn & 1);   // lands during mma below
            asm volatile("cp.async.commit_group;");
        }
        const unsigned* As = Abuf[qn & 1];
        float acc[8][4];
        #pragma unroll
        for (int nt = 0; nt < 8; nt++)
            #pragma unroll
            for (int e = 0; e < 4; e++) acc[nt][e] = 0.f;
        #pragma unroll
        for (int ks = 0; ks < 4; ks++) {
            int k8 = ks * 8;
            unsigned a[4];
            int rr = wm * 16 + g;
            a[0] = As[rr * 36 + k8 + q];
            a[1] = As[(rr + 8) * 36 + k8 + q];
            a[2] = As[rr * 36 + k8 + q + 4];
            a[3] = As[(rr + 8) * 36 + k8 + q + 4];
            #pragma unroll
            for (int nt = 0; nt < 8; nt++) {
                int cn = wn * 64 + nt * 8 + g;
                unsigned b[2];
                b[0] = Bs[(k8 + q) * 136 + cn];
                b[1] = Bs[(k8 + q + 4) * 136 + cn];
                MMA_F16(acc[nt], a, b);
            }
        }
        if (qn == 0) {
            #pragma unroll
            for (int nt = 0; nt < 8; nt++)
                #pragma unroll
                for (int e = 0; e < 4; e++) mx[nt][e] = acc[nt][e];
        } else {
            #pragma unroll
            for (int nt = 0; nt < 8; nt++)
                #pragma unroll
                for (int e = 0; e < 4; e++) mx[nt][e] = fmaxf(mx[nt][e], acc[nt][e]);
        }
    }

    #pragma unroll
    for (int hh = 0; hh < 2; hh++) {
        int pl = wm * 16 + g + hh * 8;
        size_t row = (half == 0) ? (size_t)(p * 64 + pl)
                                 : (size_t)(NP + p * 64 + pl);
        #pragma unroll
        for (int nt = 0; nt < 8; nt++) {
            int col = wn * 64 + nt * 8 + q * 2;
            float v0 = fmaxf(mx[nt][hh * 2 + 0] + cb2[col], 0.f);
            float v1 = fmaxf(mx[nt][hh * 2 + 1] + cb2[col + 1], 0.f);
            g_posfeah[row * 64 + (col >> 1)] = __floats2half2_rn(v0, v1);
        }
    }
}

// ------- pipelined fp16 GEMM, 128x256 tile (g1: K=128, Nn=512) ---------------
__global__ void __launch_bounds__(256)
gemm_g1h(const float* __restrict__ bias, const float* __restrict__ lfE)
{
    extern __shared__ float psm[];
    unsigned* Asm[2] = { (unsigned*)psm, (unsigned*)psm + 2560 };
    unsigned* Bsm[2] = { (unsigned*)psm + 5120, (unsigned*)psm + 5120 + 4224 };
    const int t = threadIdx.x;
    const int warp = t >> 5, lane = t & 31;
    const int g = lane >> 2, q = lane & 3;
    const int wm = warp >> 1, wn = warp & 1;
    const int bm = blockIdx.y * 128, bn = blockIdx.x * 256;
    const unsigned* Au = (const unsigned*)g_posfeah;   // [M2][64] half2
    const unsigned* Bu = (const unsigned*)g_wt1h;      // [64][512] half2

    float c[2][16][4];
    #pragma unroll
    for (int i = 0; i < 2; i++)
        #pragma unroll
        for (int j = 0; j < 16; j++)
            #pragma unroll
            for (int e = 0; e < 4; e++) c[i][j][e] = 0.f;

    {
        #pragma unroll
        for (int i = 0; i < 2; i++) {
            int e = t + i * 256; int r = e >> 2, cu = (e & 3) * 4;
            cp16(&Asm[0][r * 20 + cu], Au + (size_t)(bm + r) * 64 + cu);
        }
        #pragma unroll
        for (int i = 0; i < 4; i++) {
            int e = t + i * 256; int r = e >> 6, cu = (e & 63) * 4;
            cp16(&Bsm[0][r * 264 + cu], Bu + (size_t)r * 512 + bn + cu);
        }
        asm volatile("cp.async.commit_group;");
    }

    for (int tt = 0; tt < 4; tt++) {
        if (tt + 1 < 4) {
            int s = (tt + 1) & 1;
            int kk0 = (tt + 1) * 16;
            #pragma unroll
            for (int i = 0; i < 2; i++) {
                int e = t + i * 256; int r = e >> 2, cu = (e & 3) * 4;
                cp16(&Asm[s][r * 20 + cu], Au + (size_t)(bm + r) * 64 + kk0 + cu);
            }
            #pragma unroll
            for (int i = 0; i < 4; i++) {
                int e = t + i * 256; int r = e >> 6, cu = (e & 63) * 4;
                cp16(&Bsm[s][r * 264 + cu], Bu + (size_t)(kk0 + r) * 512 + bn + cu);
            }
            asm volatile("cp.async.commit_group;");
            asm volatile("cp.async.wait_group 1;");
        } else {
            asm volatile("cp.async.wait_group 0;");
        }
        __syncthreads();
        const unsigned* As = Asm[tt & 1];
        const unsigned* Bs = Bsm[tt & 1];
        #pragma unroll
        for (int ks = 0; ks < 2; ks++) {
            int k8 = ks * 8;
            unsigned a[2][4];
            #pragma unroll
            for (int mt = 0; mt < 2; mt++) {
                int r = wm * 32 + mt * 16 + g;
                a[mt][0] = As[r * 20 + k8 + q];
                a[mt][1] = As[(r + 8) * 20 + k8 + q];
                a[mt][2] = As[r * 20 + k8 + q + 4];
                a[mt][3] = As[(r + 8) * 20 + k8 + q + 4];
            }
            #pragma unroll
            for (int nt = 0; nt < 16; nt++) {
                int cn = wn * 128 + nt * 8 + g;
                unsigned b[2];
                b[0] = Bs[(k8 + q) * 264 + cn];
                b[1] = Bs[(k8 + q + 4) * 264 + cn];
                MMA_F16(c[0][nt], a[0], b);
                MMA_F16(c[1][nt], a[1], b);
            }
        }
        __syncthreads();
    }

    #pragma unroll
    for (int mt = 0; mt < 2; mt++) {
        #pragma unroll
        for (int half = 0; half < 2; half++) {
            int row = bm + wm * 32 + mt * 16 + half * 8 + g;
            int rowp = (row < NP) ? (row >> 6) : ((row - NP) >> 6);
            #pragma unroll
            for (int nt = 0; nt < 16; nt++) {
                int col = bn + wn * 128 + nt * 8 + q * 2;
                float v0 = c[mt][nt][half * 2 + 0] + bias[col] + lfE[(size_t)rowp * 512 + col];
                float v1 = c[mt][nt][half * 2 + 1] + bias[col + 1] + lfE[(size_t)rowp * 512 + col + 1];
                g_g1h[(size_t)row * 256 + (col >> 1)] =
                    __floats2half2_rn(fmaxf(v0, 0.f), fmaxf(v1, 0.f));
            }
        }
    }
}

// ------- g2 fp16 (128x256 tile, K=512, 3-stage) fused with rot + outputs -----
__global__ void __launch_bounds__(256)
gemm_g2rot(const float* __restrict__ mb2, const float* __restrict__ mw3,
           const float* __restrict__ mb3, const float* __restrict__ pos,
           float* __restrict__ out)
{
    extern __shared__ float psm[];
    unsigned* Asm[3] = { (unsigned*)psm, (unsigned*)psm + 2560, (unsigned*)psm + 5120 };
    unsigned* Bsm[3] = { (unsigned*)psm + 7680, (unsigned*)psm + 7680 + 4224,
                         (unsigned*)psm + 7680 + 8448 };
    const int t = threadIdx.x;
    const int warp = t >> 5, lane = t & 31;
    const int g = lane >> 2, q = lane & 3;
    const int wm = warp >> 1, wn = warp & 1;
    const int bm = blockIdx.x * 128;
    const unsigned* Au = (const unsigned*)g_g1h;    // [M2][256] half2
    const unsigned* Bu = (const unsigned*)g_wt2h;   // [256][256] half2

    float c[2][16][4];
    #pragma unroll
    for (int i = 0; i < 2; i++)
        #pragma unroll
        for (int j = 0; j < 16; j++)
            #pragma unroll
            for (int e = 0; e < 4; e++) c[i][j][e] = 0.f;

    auto issue = [&](int tt) {
        int s = tt % 3;
        int kk0 = tt * 16;
        #pragma unroll
        for (int i = 0; i < 2; i++) {
            int e = t + i * 256; int r = e >> 2, cu = (e & 3) * 4;
            cp16(&Asm[s][r * 20 + cu], Au + (size_t)(bm + r) * 256 + kk0 + cu);
        }
        #pragma unroll
        for (int i = 0; i < 4; i++) {
            int e = t + i * 256; int r = e >> 6, cu = (e & 63) * 4;
            cp16(&Bsm[s][r * 264 + cu], Bu + (size_t)(kk0 + r) * 256 + cu);
        }
    };

    issue(0); asm volatile("cp.async.commit_group;");
    issue(1); asm volatile("cp.async.commit_group;");

    for (int tt = 0; tt < 16; tt++) {
        if (tt + 1 < 16) { asm volatile("cp.async.wait_group 1;"); }
        else             { asm volatile("cp.async.wait_group 0;"); }
        __syncthreads();     // buf tt ready; prev mma done
        if (tt + 2 < 16) {
            issue(tt + 2);   // overlaps mma(tt)
            asm volatile("cp.async.commit_group;");
        }
        const unsigned* As = Asm[tt % 3];
        const unsigned* Bs = Bsm[tt % 3];
        #pragma unroll
        for (int ks = 0; ks < 2; ks++) {
            int k8 = ks * 8;
            unsigned a[2][4];
            #pragma unroll
            for (int mt = 0; mt < 2; mt++) {
                int r = wm * 32 + mt * 16 + g;
                a[mt][0] = As[r * 20 + k8 + q];
                a[mt][1] = As[(r + 8) * 20 + k8 + q];
                a[mt][2] = As[r * 20 + k8 + q + 4];
                a[mt][3] = As[(r + 8) * 20 + k8 + q + 4];
            }
            #pragma unroll
            for (int nt = 0; nt < 16; nt++) {
                int cn = wn * 128 + nt * 8 + g;
                unsigned b[2];
                b[0] = Bs[(k8 + q) * 264 + cn];
                b[1] = Bs[(k8 + q + 4) * 264 + cn];
                MMA_F16(c[0][nt], a[0], b);
                MMA_F16(c[1][nt], a[1], b);
            }
        }
    }
    __syncthreads();   // all mma done before smem reuse

    // epilogue: v = relu(c + mb2); partial dots with mw3; reduce 8 slots/row
    float* sred = psm;   // 128 rows * 8 slots * 9 = 9216 floats
    #pragma unroll
    for (int mt = 0; mt < 2; mt++) {
        #pragma unroll
        for (int half = 0; half < 2; half++) {
            int row_l = wm * 32 + mt * 16 + half * 8 + g;
            float p9[9];
            #pragma unroll
            for (int j = 0; j < 9; j++) p9[j] = 0.f;
            #pragma unroll
            for (int nt = 0; nt < 16; nt++) {
                int col = wn * 128 + nt * 8 + q * 2;
                float v0 = fmaxf(c[mt][nt][half * 2 + 0] + mb2[col], 0.f);
                float v1 = fmaxf(c[mt][nt][half * 2 + 1] + mb2[col + 1], 0.f);
                #pragma unroll
                for (int j = 0; j < 9; j++)
                    p9[j] += v0 * mw3[col * 9 + j] + v1 * mw3[(col + 1) * 9 + j];
            }
            int slot = wn * 4 + q;
            #pragma unroll
            for (int j = 0; j < 9; j++)
                sred[(row_l * 8 + slot) * 9 + j] = p9[j];
        }
    }
    __syncthreads();
    if (t < 128) {
        float r9[9];
        #pragma unroll
        for (int j = 0; j < 9; j++) {
            float s = 0.f;
            #pragma unroll
            for (int sl = 0; sl < 8; sl++) s += sred[(t * 8 + sl) * 9 + j];
            r9[j] = fmaxf(s + mb3[j], 0.f);
        }
        int n = bm + t;
        float* oc = out + (size_t)16 * M2 * 3 + (size_t)n * 9;
        #pragma unroll
        for (int i = 0; i < 3; i++)
            #pragma unroll
            for (int j = 0; j < 3; j++)
                oc[i * 3 + j] = r9[0 + i] * r9[0 + j] + r9[3 + i] * r9[3 + j] + r9[6 + i] * r9[6 + j];
        const float XV[4] = {-0.2f, -0.066666666666666666f, 0.066666666666666666f, 0.2f};
        #pragma unroll
        for (int t4 = 0; t4 < 16; t4++) {
            float nx = XV[t4 & 3], ny = XV[t4 >> 2];
            int m = (n * 16 + t4) & (M2 - 1);
            float cx, cy, cz;
            if (m < NP) { cx = pos[m * 3]; cy = pos[m * 3 + 1]; cz = pos[m * 3 + 2]; }
            else { int mm = m - NP; cx = g_npos[mm * 3]; cy = g_npos[mm * 3 + 1]; cz = g_npos[mm * 3 + 2]; }
            float* op = out + (size_t)(n * 16 + t4) * 3;
            op[0] = r9[0] * nx + r9[1] * ny + cx;
            op[1] = r9[3] * nx + r9[4] * ny + cy;
            op[2] = r9[6] * nx + r9[7] * ny + cz;
        }
    }
}

// ---------------- host launcher ----------------------------------------------
extern "C" void kernel_launch(void* const* d_in, const int* in_sizes, int n_in,
                              void* d_out, int out_size)
{
    const float* pos = (const float*)d_in[1];
    const float* lfea = (const float*)d_in[4];
    const float* sw1 = (const float*)d_in[5];
    const float* sb1 = (const float*)d_in[6];
    const float* sw2 = (const float*)d_in[7];
    const float* sb2 = (const float*)d_in[8];
    const float* sw3 = (const float*)d_in[9];
    const float* sb3 = (const float*)d_in[10];
    const float* cw1 = (const float*)d_in[11];
    const float* cb1 = (const float*)d_in[12];
    const float* cw2 = (const float*)d_in[13];
    const float* cb2 = (const float*)d_in[14];
    const float* mw1 = (const float*)d_in[15];
    const float* mb1 = (const float*)d_in[16];
    const float* mw2 = (const float*)d_in[17];
    const float* mb2 = (const float*)d_in[18];
    const float* mw3 = (const float*)d_in[19];
    const float* mb3 = (const float*)d_in[20];
    float* out = (float*)d_out;

    float* p_lf_m1;
    cudaGetSymbolAddress((void**)&p_lf_m1, g_lf_m1);

    cudaFuncSetAttribute(tc3mega, cudaFuncAttributeMaxDynamicSharedMemorySize, 56576);
    cudaFuncSetAttribute(k_edge2, cudaFuncAttributeMaxDynamicSharedMemorySize, 68608);
    cudaFuncSetAttribute(gemm_g1h, cudaFuncAttributeMaxDynamicSharedMemorySize, 54272);
    cudaFuncSetAttribute(gemm_g2rot, cudaFuncAttributeMaxDynamicSharedMemorySize, 81408);

    // 1-2. fused lf GEMM (virtual N=768) split-K + reduce (+weight pack +sb1 fold)
    gemm_sk2<<<dim3(12, 4, 6), 256>>>(lfea, sw1, mw1);
    k_red2<<<768, 256>>>(sb1, mw1 + 768 * 512, mw2, cw2, sw2);
    // 3. mega: h1 -> h2 (fp16 hi/lo, staged pipeline) -> n_pos -> KNN -> U/V
    tc3mega<<<dim3(1, 128), 256, 56576>>>(pos, sw1, sb2, sw3, sb3, cw1, cb1);
    // 4. edge MLP phase-B (cp.async-staged gather, fp16 mma)
    k_edge2<<<512, 256, 68608>>>(cb2);
    // 5. g1 = relu(pos_fea @ mw1' + lf_m1[p] + mb1) — fp16 mma
    gemm_g1h<<<dim3(2, 256), 256, 54272>>>(mb1, p_lf_m1);
    // 6. g2 + rot + outputs, all fused — fp16 mma, 3-stage pipeline
    gemm_g2rot<<<256, 256, 81408>>>(mb2, mw3, mb3, pos, out);
}

// round 16
// speedup vs baseline: 1.0825x; 1.0825x over previous
#include <cuda_runtime.h>
#include <cuda_fp16.h>
#include <math.h>

#define PB  256
#define PTc 64
#define NP  16384      // N = P*PT
#define M2  32768      // 2N
#define R2C 0.09f

// ---------------- scratch (static device globals; no allocations) ------------
__device__ float g_lf_s1[PB * 256];          // includes +sb1 (folded in k_red2)
__device__ float g_lf_m1[PB * 512];
__device__ float g_npos[NP * 3];
__device__ int   g_nbr[M2 * 9];
__device__ float g_U[(size_t)M2 * 64];
__device__ float g_V[(size_t)M2 * 64];
__device__ __half2 g_posfeah[(size_t)M2 * 64];   // pos_fea, K-pair packed
__device__ __half2 g_g1h[(size_t)M2 * 256];      // g1, K-pair packed
__device__ float g_part[6 * 256 * 768];
__device__ __half2 g_wt1h[64 * 512];    // mw1[768:] K-pair packed fp16
__device__ __half2 g_wt2h[256 * 256];   // mw2 K-pair packed fp16
__device__ __half2 g_wt3h[32 * 128];    // cw2 K-pair packed fp16
__device__ __half2 g_w2hh[128 * 128];   // sw2 hi, K-pair packed
__device__ __half2 g_w2lh[128 * 128];   // sw2 lo residual, K-pair packed

#define MMA_F16(cc, aa, bb) \
    asm volatile("mma.sync.aligned.m16n8k16.row.col.f32.f16.f16.f32 " \
        "{%0,%1,%2,%3},{%4,%5,%6,%7},{%8,%9},{%0,%1,%2,%3};" \
        : "+f"(cc[0]), "+f"(cc[1]), "+f"(cc[2]), "+f"(cc[3]) \
        : "r"(aa[0]), "r"(aa[1]), "r"(aa[2]), "r"(aa[3]), "r"(bb[0]), "r"(bb[1]))

__device__ __forceinline__ void cp16(void* dst, const void* src) {
    unsigned d = (unsigned)__cvta_generic_to_shared(dst);
    asm volatile("cp.async.cg.shared.global [%0], [%1], 16;" :: "r"(d), "l"(src));
}

__device__ __forceinline__ unsigned h2u(__half2 h) {
    union { __half2 h; unsigned u; } v; v.h = h; return v.u;
}

// ------- fused lf GEMM: A=lfea[256x768], virtual B = [sw1 | mw1] (N=768) -----
__global__ void gemm_sk2(const float* __restrict__ A, const float* __restrict__ sw1,
                         const float* __restrict__ mw1)
{
    __shared__ float As[64][17];
    __shared__ float Bs[16][65];
    const int bm = blockIdx.y * 64, bn = blockIdx.x * 64;
    const float* B; int Nn, coloff;
    if (bn < 256) { B = sw1; Nn = 256; coloff = bn; }
    else          { B = mw1; Nn = 512; coloff = bn - 256; }
    const int t = threadIdx.x;
    const int ty = t >> 4, tx = t & 15;
    float acc[4][4] = {};
    int kbeg = blockIdx.z * 128, kend = kbeg + 128;
    for (int k0 = kbeg; k0 < kend; k0 += 16) {
        #pragma unroll
        for (int i = 0; i < 4; i++) {
            int e = t + i * 256; int r = e >> 4, c = e & 15;
            As[r][c] = A[(size_t)(bm + r) * 768 + k0 + c];
        }
        #pragma unroll
        for (int i = 0; i < 4; i++) {
            int e = t + i * 256; int r = e >> 6, c = e & 63;
            Bs[r][c] = B[(size_t)(k0 + r) * Nn + coloff + c];
        }
        __syncthreads();
        #pragma unroll
        for (int kk = 0; kk < 16; kk++) {
            float a[4], b[4];
            #pragma unroll
            for (int i = 0; i < 4; i++) a[i] = As[ty * 4 + i][kk];
            #pragma unroll
            for (int j = 0; j < 4; j++) b[j] = Bs[kk][tx * 4 + j];
            #pragma unroll
            for (int i = 0; i < 4; i++)
                #pragma unroll
                for (int j = 0; j < 4; j++)
                    acc[i][j] += a[i] * b[j];
        }
        __syncthreads();
    }
    float* Cz = g_part + (size_t)blockIdx.z * 256 * 768;
    #pragma unroll
    for (int i = 0; i < 4; i++)
        #pragma unroll
        for (int j = 0; j < 4; j++)
            Cz[(size_t)(bm + ty * 4 + i) * 768 + bn + tx * 4 + j] = acc[i][j];
}

// ------- reduce split-K + (folded) weight packing + sb1 fold -----------------
__global__ void k_red2(const float* __restrict__ sb1, const float* __restrict__ w1,
                       const float* __restrict__ w2, const float* __restrict__ w3,
                       const float* __restrict__ sw2)
{
    int e = blockIdx.x * 256 + threadIdx.x;   // < 196608
    float s = 0.f;
    #pragma unroll
    for (int z = 0; z < 6; z++) s += g_part[(size_t)z * 196608 + e];
    int row = e / 768, col = e - row * 768;
    if (col < 256) g_lf_s1[row * 256 + col] = s + sb1[col];
    else           g_lf_m1[row * 512 + col - 256] = s;

    // folded weight packing (same thread-id space)
    int i = e;
    if (i < 32768) {                       // wt1h: [64 kk][512 n]
        int kk = i >> 9, n = i & 511;
        g_wt1h[i] = __floats2half2_rn(w1[(2 * kk) * 512 + n], w1[(2 * kk + 1) * 512 + n]);
    } else if (i < 98304) {                // wt2h: [256 kk][256 n]
        int e2 = i - 32768; int kk = e2 >> 8, n = e2 & 255;
        g_wt2h[e2] = __floats2half2_rn(w2[(2 * kk) * 256 + n], w2[(2 * kk + 1) * 256 + n]);
    } else if (i < 102400) {               // wt3h: [32 kk][128 n]
        int e2 = i - 98304; int kk = e2 >> 7, n = e2 & 127;
        g_wt3h[e2] = __floats2half2_rn(w3[(2 * kk) * 128 + n], w3[(2 * kk + 1) * 128 + n]);
    } else if (i < 118784) {               // sw2 hi/lo: [128 kk][128 n]
        int e2 = i - 102400; int kk = e2 >> 7, n = e2 & 127;
        float f0 = sw2[(2 * kk) * 128 + n], f1 = sw2[(2 * kk + 1) * 128 + n];
        __half h0 = __float2half_rn(f0), h1 = __float2half_rn(f1);
        g_w2hh[e2] = __halves2half2(h0, h1);
        g_w2lh[e2] = __floats2half2_rn(f0 - __half2float(h0), f1 - __half2float(h1));
    }
}

// ------- mega: h1 on-the-fly -> fp16-split h2 GEMM -> n_pos -> KNN -> U/V ----
// block = 128 rows = 2 complete batches; cp.async staged A-inputs + B, 2-deep
__global__ void __launch_bounds__(256)
tc3mega(const float* __restrict__ pos, const float* __restrict__ sw1,
        const float* __restrict__ sb2, const float* __restrict__ sw3,
        const float* __restrict__ sb3, const float* __restrict__ cw1,
        const float* __restrict__ cb1)
{
    extern __shared__ unsigned sm3[];
    unsigned* Ah = sm3;                        // [128][20] half2
    unsigned* Al = Ah + 2560;                  // [128][20]
    unsigned* BhB[2] = { Al + 2560, Al + 2560 + 2176 };          // each [16][136]
    unsigned* BlB[2] = { Al + 2560 + 4352, Al + 2560 + 6528 };   // each [16][136]
    float* stageB = (float*)(Al + 2560 + 8704);                  // 2 x 160 floats
    const int t = threadIdx.x;
    const int warp = t >> 5, lane = t & 31;
    const int g = lane >> 2, q = lane & 3;
    const int wm = warp >> 1, wn = warp & 1;
    const int bm = blockIdx.y * 128;
    const int p0 = bm >> 6;

    float c[2][8][4];
    #pragma unroll
    for (int i = 0; i < 2; i++)
        #pragma unroll
        for (int j = 0; j < 8; j++)
            #pragma unroll
            for (int e = 0; e < 4; e++) c[i][j][e] = 0.f;

    const int rA = t >> 3, c4A = (t & 7) * 4;
    float pxr[4], pyr[4], pzr[4];
    #pragma unroll
    for (int i = 0; i < 4; i++) {
        int row = bm + rA + i * 32;
        pxr[i] = pos[row * 3]; pyr[i] = pos[row * 3 + 1]; pzr[i] = pos[row * 3 + 2];
    }

    auto issue = [&](int tt) {
        int s = tt & 1;
        int kk0 = tt * 16, k0 = tt * 32;
        #pragma unroll
        for (int i = 0; i < 2; i++) {
            int e = t + i * 256; int r = e >> 5, cu = (e & 31) * 4;
            cp16(&BhB[s][r * 136 + cu], (const unsigned*)g_w2hh + (size_t)(kk0 + r) * 128 + cu);
            cp16(&BlB[s][r * 136 + cu], (const unsigned*)g_w2lh + (size_t)(kk0 + r) * 128 + cu);
        }
        if (t < 40) {
            int seg = t >> 3, off = (t & 7) * 4;
            const float* src;
            if (seg == 0)      src = g_lf_s1 + p0 * 256 + k0 + off;
            else if (seg == 1) src = g_lf_s1 + (p0 + 1) * 256 + k0 + off;
            else               src = sw1 + (size_t)(768 + seg - 2) * 256 + k0 + off;
            cp16(&stageB[s * 160 + seg * 32 + off], src);
        }
    };

    issue(0);
    asm volatile("cp.async.commit_group;");

    for (int tt = 0; tt < 8; tt++) {
        asm volatile("cp.async.wait_group 0;");
        __syncthreads();
        if (tt + 1 < 8) {
            issue(tt + 1);
            asm volatile("cp.async.commit_group;");
        }
        {
            const float* st = stageB + (tt & 1) * 160;
            float4 w0 = *(const float4*)(st + 64 + c4A);
            float4 w1 = *(const float4*)(st + 96 + c4A);
            float4 w2 = *(const float4*)(st + 128 + c4A);
            float4 lf0 = *(const float4*)(st + c4A);
            float4 lf1 = *(const float4*)(st + 32 + c4A);
            #pragma unroll
            for (int i = 0; i < 4; i++) {
                int r = rA + i * 32;
                float4 lf = (i < 2) ? lf0 : lf1;
                float px = pxr[i], py = pyr[i], pz = pzr[i];
                float h0 = fmaxf(lf.x + px * w0.x + py * w1.x + pz * w2.x, 0.f);
                float h1v = fmaxf(lf.y + px * w0.y + py * w1.y + pz * w2.y, 0.f);
                float h2v = fmaxf(lf.z + px * w0.z + py * w1.z + pz * w2.z, 0.f);
                float h3 = fmaxf(lf.w + px * w0.w + py * w1.w + pz * w2.w, 0.f);
                __half2 hiA = __floats2half2_rn(h0, h1v);
                __half2 hiB = __floats2half2_rn(h2v, h3);
                float2 fA = __half22float2(hiA), fB = __half22float2(hiB);
                __half2 loA = __floats2half2_rn(h0 - fA.x, h1v - fA.y);
                __half2 loB = __floats2half2_rn(h2v - fB.x, h3 - fB.y);
                int idx = r * 20 + (c4A >> 1);
                *(uint2*)&Ah[idx] = make_uint2(h2u(hiA), h2u(hiB));
                *(uint2*)&Al[idx] = make_uint2(h2u(loA), h2u(loB));
            }
        }
        __syncthreads();
        const unsigned* Bh = BhB[tt & 1];
        const unsigned* Bl = BlB[tt & 1];
        #pragma unroll
        for (int ks = 0; ks < 2; ks++) {
            int k8 = ks * 8;
            unsigned ah[2][4], al[2][4];
            #pragma unroll
            for (int mt = 0; mt < 2; mt++) {
                int r = wm * 32 + mt * 16 + g;
                ah[mt][0] = Ah[r * 20 + k8 + q];       al[mt][0] = Al[r * 20 + k8 + q];
                ah[mt][1] = Ah[(r + 8) * 20 + k8 + q]; al[mt][1] = Al[(r + 8) * 20 + k8 + q];
                ah[mt][2] = Ah[r * 20 + k8 + q + 4];   al[mt][2] = Al[r * 20 + k8 + q + 4];
                ah[mt][3] = Ah[(r + 8) * 20 + k8 + q + 4]; al[mt][3] = Al[(r + 8) * 20 + k8 + q + 4];
            }
            #pragma unroll
            for (int nt = 0; nt < 8; nt++) {
                int cn = wn * 64 + nt * 8 + g;
                unsigned bh[2], bl[2];
                bh[0] = Bh[(k8 + q) * 136 + cn];     bh[1] = Bh[(k8 + q + 4) * 136 + cn];
                bl[0] = Bl[(k8 + q) * 136 + cn];     bl[1] = Bl[(k8 + q + 4) * 136 + cn];
                #pragma unroll
                for (int mt = 0; mt < 2; mt++) {
                    MMA_F16(c[mt][nt], al[mt], bh);
                    MMA_F16(c[mt][nt], ah[mt], bl);
                    MMA_F16(c[mt][nt], ah[mt], bh);
                }
            }
        }
    }
    __syncthreads();

    // ---- phase 2: n_pos via smem reduction ----
    float* fsm = (float*)sm3;
    float* sred = fsm;                 // 128*8*3
    float* snp  = fsm + 3072;          // 128*3
    float* sx   = fsm + 3456;          // 256
    float* sy   = fsm + 3712;
    float* sz   = fsm + 3968;
    float* scw1 = fsm + 4224;          // 384
    float* scb1 = fsm + 4608;          // 64
    #pragma unroll
    for (int mt = 0; mt < 2; mt++) {
        #pragma unroll
        for (int half = 0; half < 2; half++) {
            int row_l = wm * 32 + mt * 16 + half * 8 + g;
            float p0v = 0.f, p1 = 0.f, p2 = 0.f;
            #pragma unroll
            for (int nt = 0; nt < 8; nt++) {
                int col = wn * 64 + nt * 8 + q * 2;
                float v0 = fmaxf(c[mt][nt][half * 2 + 0] + sb2[col], 0.f);
                float v1 = fmaxf(c[mt][nt][half * 2 + 1] + sb2[col + 1], 0.f);
                p0v += v0 * sw3[col * 3]     + v1 * sw3[(col + 1) * 3];
                p1 += v0 * sw3[col * 3 + 1] + v1 * sw3[(col + 1) * 3 + 1];
                p2 += v0 * sw3[col * 3 + 2] + v1 * sw3[(col + 1) * 3 + 2];
            }
            int slot = wn * 4 + q;
            sred[(row_l * 8 + slot) * 3 + 0] = p0v;
            sred[(row_l * 8 + slot) * 3 + 1] = p1;
            sred[(row_l * 8 + slot) * 3 + 2] = p2;
        }
    }
    __syncthreads();
    if (t < 128) {
        float a0 = 0.f, a1 = 0.f, a2 = 0.f;
        #pragma unroll
        for (int s = 0; s < 8; s++) {
            a0 += sred[(t * 8 + s) * 3 + 0];
            a1 += sred[(t * 8 + s) * 3 + 1];
            a2 += sred[(t * 8 + s) * 3 + 2];
        }
        int row = bm + t;
        float n0 = tanhf(fmaxf(a0 + sb3[0], 0.f)) + pos[row * 3 + 0];
        float n1 = tanhf(fmaxf(a1 + sb3[1], 0.f)) + pos[row * 3 + 1];
        float n2 = tanhf(fmaxf(a2 + sb3[2], 0.f)) + pos[row * 3 + 2];
        g_npos[row * 3 + 0] = n0; g_npos[row * 3 + 1] = n1; g_npos[row * 3 + 2] = n2;
        snp[t * 3 + 0] = n0; snp[t * 3 + 1] = n1; snp[t * 3 + 2] = n2;
    }
    __syncthreads();

    // ---- phase 3: KNN for the 2 batches + U/V ----
    int b = t >> 7, i = t & 127;
    int rowl = b * 64 + (i & 63);
    float x, y, z;
    if (i < 64) {
        int gr = bm + rowl;
        x = pos[gr * 3]; y = pos[gr * 3 + 1]; z = pos[gr * 3 + 2];
    } else {
        x = snp[rowl * 3]; y = snp[rowl * 3 + 1]; z = snp[rowl * 3 + 2];
    }
    sx[b * 128 + i] = x; sy[b * 128 + i] = y; sz[b * 128 + i] = z;
    for (int e = t; e < 448; e += 256) {
        if (e < 384) scw1[e] = cw1[e]; else scb1[e - 384] = cb1[e - 384];
    }
    __syncthreads();

    unsigned long long bk[9];
    #pragma unroll
    for (int qq = 0; qq < 9; qq++) bk[qq] = 0xFFFFFFFFFFFFFFFFull;
    const float* sxb = sx + b * 128; const float* syb = sy + b * 128; const float* szb = sz + b * 128;
    for (int j = 0; j < 128; j++) {
        float dx = x - sxb[j], dy = y - syb[j], dz = z - szb[j];
        float d2 = dx * dx + dy * dy + dz * dz;
        if (d2 <= R2C) {
            unsigned long long key = ((unsigned long long)__float_as_uint(d2) << 32) | (unsigned)j;
            if (key < bk[8]) {
                bk[8] = key;
                #pragma unroll
                for (int qq = 8; qq > 0; qq--)
                    if (bk[qq] < bk[qq - 1]) {
                        unsigned long long tmp = bk[qq]; bk[qq] = bk[qq - 1]; bk[qq - 1] = tmp;
                    }
            }
        }
    }
    int ptg = (p0 + b) * 128 + i;
    int bi0 = (int)(unsigned)bk[0];
    #pragma unroll
    for (int qq = 0; qq < 9; qq++)
        g_nbr[ptg * 9 + qq] = (bk[qq] != 0xFFFFFFFFFFFFFFFFull) ? (int)(unsigned)bk[qq] : bi0;

    for (int e = t; e < 256 * 64; e += 256) {
        int ptl = e >> 6, k = e & 63;
        float xx = sx[ptl], yy = sy[ptl], zz = sz[ptl];
        float wn0 = scw1[k],       wn1 = scw1[64 + k],  wn2 = scw1[128 + k];
        float wr0 = scw1[192 + k], wr1 = scw1[256 + k], wr2 = scw1[320 + k];
        int ptgl = (p0 + (ptl >> 7)) * 128 + (ptl & 127);
        g_U[(size_t)ptgl * 64 + k] = scb1[k] + xx * (wn0 + wr0) + yy * (wn1 + wr1) + zz * (wn2 + wr2);
        g_V[(size_t)ptgl * 64 + k] = xx * wr0 + yy * wr1 + zz * wr2;
    }
}

// ------- edge MLP phase-B: whole-batch U staged in smem + fp16 mma -----------
__global__ void __launch_bounds__(256)
k_edge2(const float* __restrict__ cb2)
{
    extern __shared__ unsigned esm[];
    float*    Us = (float*)esm;                  // [128][68] fp32 = 34816 B
    unsigned* Bs = esm + 8704;                   // [32][136] half2 = 17408 B
    unsigned* Abuf[2] = { esm + 8704 + 4352, esm + 8704 + 4352 + 2304 };  // [64][36] x2
    const int t = threadIdx.x;
    const int warp = t >> 5, lane = t & 31;
    const int g = lane >> 2, q = lane & 3;
    const int wm = warp >> 1, wn = warp & 1;
    const int p = blockIdx.x >> 1, half = blockIdx.x & 1;
    const int ptbase = p * 128 + half * 64;
    const int r4 = t >> 2, q4 = t & 3;

    // stage the whole batch's U table (coalesced) + Bs weights
    #pragma unroll
    for (int i = 0; i < 8; i++) {
        int e = t + i * 256; int r = e >> 4, cc = (e & 15) * 4;
        cp16(&Us[r * 68 + cc], g_U + (size_t)(p * 128 + r) * 64 + cc);
    }
    #pragma unroll
    for (int i = 0; i < 4; i++) {
        int e = t + i * 256;   // 1024 chunks of 16B = [32][128] half2
        int r = e >> 5, cc = (e & 31) * 4;
        cp16(&Bs[r * 136 + cc], (const unsigned*)g_wt3h + (size_t)r * 128 + cc);
    }
    asm volatile("cp.async.commit_group;");

    int nbr9[9];
    #pragma unroll
    for (int qq = 0; qq < 9; qq++) nbr9[qq] = g_nbr[(ptbase + r4) * 9 + qq];

    float vv[16];
    {
        const float4* Vr = (const float4*)(g_V + (size_t)(ptbase + r4) * 64 + q4 * 16);
        #pragma unroll
        for (int j4 = 0; j4 < 4; j4++) {
            float4 v = Vr[j4];
            vv[j4 * 4 + 0] = v.x; vv[j4 * 4 + 1] = v.y;
            vv[j4 * 4 + 2] = v.z; vv[j4 * 4 + 3] = v.w;
        }
    }
    asm volatile("cp.async.wait_group 0;");
    __syncthreads();

    float mx[8][4];
    #pragma unroll 1
    for (int qn = 0; qn < 9; qn++) {
        // fill Abuf[qn&1] from smem U (pure LDS)
        {
            const float* Rr = Us + nbr9[qn] * 68 + q4 * 16;
            union { __half2 h[4]; uint4 u; } pk;
            #pragma unroll
            for (int j4 = 0; j4 < 2; j4++) {
                #pragma unroll
                for (int s = 0; s < 2; s++) {
                    float4 u = *(const float4*)(Rr + (j4 * 2 + s) * 4);
                    pk.h[s * 2 + 0] = __floats2half2_rn(fmaxf(u.x - vv[(j4 * 2 + s) * 4 + 0], 0.f),
                                                        fmaxf(u.y - vv[(j4 * 2 + s) * 4 + 1], 0.f));
                    pk.h[s * 2 + 1] = __floats2half2_rn(fmaxf(u.z - vv[(j4 * 2 + s) * 4 + 2], 0.f),
                                                        fmaxf(u.w - vv[(j4 * 2 + s) * 4 + 3], 0.f));
                }
                *(uint4*)&Abuf[qn & 1][r4 * 36 + q4 * 8 + j4 * 4] = pk.u;
            }
        }
        __syncthreads();   // Abuf[qn&1] ready
        const unsigned* As = Abuf[qn & 1];
        float acc[8][4];
        #pragma unroll
        for (int nt = 0; nt < 8; nt++)
            #pragma unroll
            for (int e = 0; e < 4; e++) acc[nt][e] = 0.f;
        #pragma unroll
        for (int ks = 0; ks < 4; ks++) {
            int k8 = ks * 8;
            unsigned a[4];
            int rr = wm * 16 + g;
            a[0] = As[rr * 36 + k8 + q];
            a[1] = As[(rr + 8) * 36 + k8 + q];
            a[2] = As[rr * 36 + k8 + q + 4];
            a[3] = As[(rr + 8) * 36 + k8 + q + 4];
            #pragma unroll
            for (int nt = 0; nt < 8; nt++) {
                int cn = wn * 64 + nt * 8 + g;
                unsigned b[2];
                b[0] = Bs[(k8 + q) * 136 + cn];
                b[1] = Bs[(k8 + q + 4) * 136 + cn];
                MMA_F16(acc[nt], a, b);
            }
        }
        if (qn == 0) {
            #pragma unroll
            for (int nt = 0; nt < 8; nt++)
                #pragma unroll
                for (int e = 0; e < 4; e++) mx[nt][e] = acc[nt][e];
        } else {
            #pragma unroll
            for (int nt = 0; nt < 8; nt++)
                #pragma unroll
                for (int e = 0; e < 4; e++) mx[nt][e] = fmaxf(mx[nt][e], acc[nt][e]);
        }
        if (qn & 1) __syncthreads();   // free buffer parity before refill (2 iters later)
    }

    #pragma unroll
    for (int hh = 0; hh < 2; hh++) {
        int pl = wm * 16 + g + hh * 8;
        size_t row = (half == 0) ? (size_t)(p * 64 + pl)
                                 : (size_t)(NP + p * 64 + pl);
        #pragma unroll
        for (int nt = 0; nt < 8; nt++) {
            int col = wn * 64 + nt * 8 + q * 2;
            float v0 = fmaxf(mx[nt][hh * 2 + 0] + cb2[col], 0.f);
            float v1 = fmaxf(mx[nt][hh * 2 + 1] + cb2[col + 1], 0.f);
            g_posfeah[row * 64 + (col >> 1)] = __floats2half2_rn(v0, v1);
        }
    }
}

// ------- pipelined fp16 GEMM, 128x256 tile (g1: K=128, Nn=512) ---------------
__global__ void __launch_bounds__(256)
gemm_g1h(const float* __restrict__ bias, const float* __restrict__ lfE)
{
    extern __shared__ float psm[];
    unsigned* Asm[2] = { (unsigned*)psm, (unsigned*)psm + 2560 };
    unsigned* Bsm[2] = { (unsigned*)psm + 5120, (unsigned*)psm + 5120 + 4224 };
    const int t = threadIdx.x;
    const int warp = t >> 5, lane = t & 31;
    const int g = lane >> 2, q = lane & 3;
    const int wm = warp >> 1, wn = warp & 1;
    const int bm = blockIdx.y * 128, bn = blockIdx.x * 256;
    const unsigned* Au = (const unsigned*)g_posfeah;
    const unsigned* Bu = (const unsigned*)g_wt1h;

    float c[2][16][4];
    #pragma unroll
    for (int i = 0; i < 2; i++)
        #pragma unroll
        for (int j = 0; j < 16; j++)
            #pragma unroll
            for (int e = 0; e < 4; e++) c[i][j][e] = 0.f;

    {
        #pragma unroll
        for (int i = 0; i < 2; i++) {
            int e = t + i * 256; int r = e >> 2, cu = (e & 3) * 4;
            cp16(&Asm[0][r * 20 + cu], Au + (size_t)(bm + r) * 64 + cu);
        }
        #pragma unroll
        for (int i = 0; i < 4; i++) {
            int e = t + i * 256; int r = e >> 6, cu = (e & 63) * 4;
            cp16(&Bsm[0][r * 264 + cu], Bu + (size_t)r * 512 + bn + cu);
        }
        asm volatile("cp.async.commit_group;");
    }

    for (int tt = 0; tt < 4; tt++) {
        if (tt + 1 < 4) {
            int s = (tt + 1) & 1;
            int kk0 = (tt + 1) * 16;
            #pragma unroll
            for (int i = 0; i < 2; i++) {
                int e = t + i * 256; int r = e >> 2, cu = (e & 3) * 4;
                cp16(&Asm[s][r * 20 + cu], Au + (size_t)(bm + r) * 64 + kk0 + cu);
            }
            #pragma unroll
            for (int i = 0; i < 4; i++) {
                int e = t + i * 256; int r = e >> 6, cu = (e & 63) * 4;
                cp16(&Bsm[s][r * 264 + cu], Bu + (size_t)(kk0 + r) * 512 + bn + cu);
            }
            asm volatile("cp.async.commit_group;");
            asm volatile("cp.async.wait_group 1;");
        } else {
            asm volatile("cp.async.wait_group 0;");
        }
        __syncthreads();
        const unsigned* As = Asm[tt & 1];
        const unsigned* Bs = Bsm[tt & 1];
        #pragma unroll
        for (int ks = 0; ks < 2; ks++) {
            int k8 = ks * 8;
            unsigned a[2][4];
            #pragma unroll
            for (int mt = 0; mt < 2; mt++) {
                int r = wm * 32 + mt * 16 + g;
                a[mt][0] = As[r * 20 + k8 + q];
                a[mt][1] = As[(r + 8) * 20 + k8 + q];
                a[mt][2] = As[r * 20 + k8 + q + 4];
                a[mt][3] = As[(r + 8) * 20 + k8 + q + 4];
            }
            #pragma unroll
            for (int nt = 0; nt < 16; nt++) {
                int cn = wn * 128 + nt * 8 + g;
                unsigned b[2];
                b[0] = Bs[(k8 + q) * 264 + cn];
                b[1] = Bs[(k8 + q + 4) * 264 + cn];
                MMA_F16(c[0][nt], a[0], b);
                MMA_F16(c[1][nt], a[1], b);
            }
        }
        __syncthreads();
    }

    #pragma unroll
    for (int mt = 0; mt < 2; mt++) {
        #pragma unroll
        for (int half = 0; half < 2; half++) {
            int row = bm + wm * 32 + mt * 16 + half * 8 + g;
            int rowp = (row < NP) ? (row >> 6) : ((row - NP) >> 6);
            #pragma unroll
            for (int nt = 0; nt < 16; nt++) {
                int col = bn + wn * 128 + nt * 8 + q * 2;
                float v0 = c[mt][nt][half * 2 + 0] + bias[col] + lfE[(size_t)rowp * 512 + col];
                float v1 = c[mt][nt][half * 2 + 1] + bias[col + 1] + lfE[(size_t)rowp * 512 + col + 1];
                g_g1h[(size_t)row * 256 + (col >> 1)] =
                    __floats2half2_rn(fmaxf(v0, 0.f), fmaxf(v1, 0.f));
            }
        }
    }
}

// ------- g2 fp16 (128x256 tile, K=512, 3-stage) fused with rot + outputs -----
__global__ void __launch_bounds__(256)
gemm_g2rot(const float* __restrict__ mb2, const float* __restrict__ mw3,
           const float* __restrict__ mb3, const float* __restrict__ pos,
           float* __restrict__ out)
{
    extern __shared__ float psm[];
    unsigned* Asm[3] = { (unsigned*)psm, (unsigned*)psm + 2560, (unsigned*)psm + 5120 };
    unsigned* Bsm[3] = { (unsigned*)psm + 7680, (unsigned*)psm + 7680 + 4224,
                         (unsigned*)psm + 7680 + 8448 };
    const int t = threadIdx.x;
    const int warp = t >> 5, lane = t & 31;
    const int g = lane >> 2, q = lane & 3;
    const int wm = warp >> 1, wn = warp & 1;
    const int bm = blockIdx.x * 128;
    const unsigned* Au = (const unsigned*)g_g1h;
    const unsigned* Bu = (const unsigned*)g_wt2h;

    float c[2][16][4];
    #pragma unroll
    for (int i = 0; i < 2; i++)
        #pragma unroll
        for (int j = 0; j < 16; j++)
            #pragma unroll
            for (int e = 0; e < 4; e++) c[i][j][e] = 0.f;

    auto issue = [&](int tt) {
        int s = tt % 3;
        int kk0 = tt * 16;
        #pragma unroll
        for (int i = 0; i < 2; i++) {
            int e = t + i * 256; int r = e >> 2, cu = (e & 3) * 4;
            cp16(&Asm[s][r * 20 + cu], Au + (size_t)(bm + r) * 256 + kk0 + cu);
        }
        #pragma unroll
        for (int i = 0; i < 4; i++) {
            int e = t + i * 256; int r = e >> 6, cu = (e & 63) * 4;
            cp16(&Bsm[s][r * 264 + cu], Bu + (size_t)(kk0 + r) * 256 + cu);
        }
    };

    issue(0); asm volatile("cp.async.commit_group;");
    issue(1); asm volatile("cp.async.commit_group;");

    for (int tt = 0; tt < 16; tt++) {
        if (tt + 1 < 16) { asm volatile("cp.async.wait_group 1;"); }
        else             { asm volatile("cp.async.wait_group 0;"); }
        __syncthreads();
        if (tt + 2 < 16) {
            issue(tt + 2);
            asm volatile("cp.async.commit_group;");
        }
        const unsigned* As = Asm[tt % 3];
        const unsigned* Bs = Bsm[tt % 3];
        #pragma unroll
        for (int ks = 0; ks < 2; ks++) {
            int k8 = ks * 8;
            unsigned a[2][4];
            #pragma unroll
            for (int mt = 0; mt < 2; mt++) {
                int r = wm * 32 + mt * 16 + g;
                a[mt][0] = As[r * 20 + k8 + q];
                a[mt][1] = As[(r + 8) * 20 + k8 + q];
                a[mt][2] = As[r * 20 + k8 + q + 4];
                a[mt][3] = As[(r + 8) * 20 + k8 + q + 4];
            }
            #pragma unroll
            for (int nt = 0; nt < 16; nt++) {
                int cn = wn * 128 + nt * 8 + g;
                unsigned b[2];
                b[0] = Bs[(k8 + q) * 264 + cn];
                b[1] = Bs[(k8 + q + 4) * 264 + cn];
                MMA_F16(c[0][nt], a[0], b);
                MMA_F16(c[1][nt], a[1], b);
            }
        }
    }
    __syncthreads();

    // epilogue: v = relu(c + mb2); partial dots with mw3; reduce 8 slots/row
    float* sred = psm;   // 128 rows * 8 slots * 9 = 9216 floats
    #pragma unroll
    for (int mt = 0; mt < 2; mt++) {
        #pragma unroll
        for (int half = 0; half < 2; half++) {
            int row_l = wm * 32 + mt * 16 + half * 8 + g;
            float p9[9];
            #pragma unroll
            for (int j = 0; j < 9; j++) p9[j] = 0.f;
            #pragma unroll
            for (int nt = 0; nt < 16; nt++) {
                int col = wn * 128 + nt * 8 + q * 2;
                float v0 = fmaxf(c[mt][nt][half * 2 + 0] + mb2[col], 0.f);
                float v1 = fmaxf(c[mt][nt][half * 2 + 1] + mb2[col + 1], 0.f);
                #pragma unroll
                for (int j = 0; j < 9; j++)
                    p9[j] += v0 * mw3[col * 9 + j] + v1 * mw3[(col + 1) * 9 + j];
            }
            int slot = wn * 4 + q;
            #pragma unroll
            for (int j = 0; j < 9; j++)
                sred[(row_l * 8 + slot) * 9 + j] = p9[j];
        }
    }
    __syncthreads();
    if (t < 128) {
        float r9[9];
        #pragma unroll
        for (int j = 0; j < 9; j++) {
            float s = 0.f;
            #pragma unroll
            for (int sl = 0; sl < 8; sl++) s += sred[(t * 8 + sl) * 9 + j];
            r9[j] = fmaxf(s + mb3[j], 0.f);
        }
        int n = bm + t;
        float* oc = out + (size_t)16 * M2 * 3 + (size_t)n * 9;
        #pragma unroll
        for (int i = 0; i < 3; i++)
            #pragma unroll
            for (int j = 0; j < 3; j++)
                oc[i * 3 + j] = r9[0 + i] * r9[0 + j] + r9[3 + i] * r9[3 + j] + r9[6 + i] * r9[6 + j];
        const float XV[4] = {-0.2f, -0.066666666666666666f, 0.066666666666666666f, 0.2f};
        #pragma unroll
        for (int t4 = 0; t4 < 16; t4++) {
            float nx = XV[t4 & 3], ny = XV[t4 >> 2];
            int m = (n * 16 + t4) & (M2 - 1);
            float cx, cy, cz;
            if (m < NP) { cx = pos[m * 3]; cy = pos[m * 3 + 1]; cz = pos[m * 3 + 2]; }
            else { int mm = m - NP; cx = g_npos[mm * 3]; cy = g_npos[mm * 3 + 1]; cz = g_npos[mm * 3 + 2]; }
            float* op = out + (size_t)(n * 16 + t4) * 3;
            op[0] = r9[0] * nx + r9[1] * ny + cx;
            op[1] = r9[3] * nx + r9[4] * ny + cy;
            op[2] = r9[6] * nx + r9[7] * ny + cz;
        }
    }
}

// ---------------- host launcher ----------------------------------------------
extern "C" void kernel_launch(void* const* d_in, const int* in_sizes, int n_in,
                              void* d_out, int out_size)
{
    const float* pos = (const float*)d_in[1];
    const float* lfea = (const float*)d_in[4];
    const float* sw1 = (const float*)d_in[5];
    const float* sb1 = (const float*)d_in[6];
    const float* sw2 = (const float*)d_in[7];
    const float* sb2 = (const float*)d_in[8];
    const float* sw3 = (const float*)d_in[9];
    const float* sb3 = (const float*)d_in[10];
    const float* cw1 = (const float*)d_in[11];
    const float* cb1 = (const float*)d_in[12];
    const float* cw2 = (const float*)d_in[13];
    const float* cb2 = (const float*)d_in[14];
    const float* mw1 = (const float*)d_in[15];
    const float* mb1 = (const float*)d_in[16];
    const float* mw2 = (const float*)d_in[17];
    const float* mb2 = (const float*)d_in[18];
    const float* mw3 = (const float*)d_in[19];
    const float* mb3 = (const float*)d_in[20];
    float* out = (float*)d_out;

    float* p_lf_m1;
    cudaGetSymbolAddress((void**)&p_lf_m1, g_lf_m1);

    cudaFuncSetAttribute(tc3mega, cudaFuncAttributeMaxDynamicSharedMemorySize, 56576);
    cudaFuncSetAttribute(k_edge2, cudaFuncAttributeMaxDynamicSharedMemorySize, 70912);
    cudaFuncSetAttribute(gemm_g1h, cudaFuncAttributeMaxDynamicSharedMemorySize, 54272);
    cudaFuncSetAttribute(gemm_g2rot, cudaFuncAttributeMaxDynamicSharedMemorySize, 81408);

    // 1-2. fused lf GEMM (virtual N=768) split-K + reduce (+weight pack +sb1 fold)
    gemm_sk2<<<dim3(12, 4, 6), 256>>>(lfea, sw1, mw1);
    k_red2<<<768, 256>>>(sb1, mw1 + 768 * 512, mw2, cw2, sw2);
    // 3. mega: h1 -> h2 (fp16 hi/lo, staged pipeline) -> n_pos -> KNN -> U/V
    tc3mega<<<dim3(1, 128), 256, 56576>>>(pos, sw1, sb2, sw3, sb3, cw1, cb1);
    // 4. edge MLP phase-B (whole-batch U in smem, fp16 mma)
    k_edge2<<<512, 256, 70912>>>(cb2);
    // 5. g1 = relu(pos_fea @ mw1' + lf_m1[p] + mb1) — fp16 mma
    gemm_g1h<<<dim3(2, 256), 256, 54272>>>(mb1, p_lf_m1);
    // 6. g2 + rot + outputs, all fused — fp16 mma, 3-stage pipeline
    gemm_g2rot<<<256, 256, 81408>>>(mb2, mw3, mb3, pos, out);
}